// round 9
// baseline (speedup 1.0000x reference)
#include <cuda_runtime.h>
#include <cuda_fp16.h>

// SampleConditionalGMM: out = stds[b, lut[label], c] * noise + means[b, lut[label], c]
// Shapes: label_map [2,160,160,160,1] i32, means/stds [2,25,2] f32,
//         noise/out [2,160,160,160,2] f32.
//
// Gather strategy: per-label table entry packed as 4x half = 8 B
// {std0, std1, mean0, mean1}, replicated 16x across bank-pairs so every
// 16-lane phase of an LDS.64 is conflict-free for ANY label mix.
// FMA stays in fp32 (only table values are fp16-rounded: rel ~5e-4 max,
// ~3e-4 in L2-norm, under the 1e-3 threshold).

#define NL 25          // number of generation labels
#define MAXL 48        // max label value + 1
#define REP 16         // replication factor (8B bank-pairs per 128B row)
#define VOX 4096000    // 160*160*160 voxels per batch
#define VPT 4          // voxels per thread
#define VPB 1024       // voxels per block (256 threads * 4)
#define BLOCKS_PER_BATCH (VOX / VPB)   // 4000

__constant__ int c_gen_labels[NL] = {
    0, 2, 3, 4, 5, 7, 8, 10, 11, 12, 13, 14, 15, 16, 17, 18,
    24, 26, 28, 41, 42, 43, 44, 46, 47
};

struct __align__(8) Entry { __half2 sd; __half2 mn; };  // {std0,std1},{mean0,mean1}

__global__ __launch_bounds__(256)
void gmm_sample_kernel(const int*   __restrict__ label,
                       const float* __restrict__ means,
                       const float* __restrict__ stds,
                       const float* __restrict__ noise,
                       float*       __restrict__ out)
{
    __shared__ Entry s_tab[MAXL * REP];   // 6144 B

    const int t = threadIdx.x;
    const int b = blockIdx.x / BLOCKS_PER_BATCH;   // batch id, constant per block

    // Fill: 25 labels x 16 replicas = 400 entries, 256 threads -> 2 rounds.
    for (int i = t; i < NL * REP; i += 256) {
        const int li  = i >> 4;        // compacted label index 0..24
        const int col = i & 15;        // replica column (bank-pair)
        const int lbl = c_gen_labels[li];
        const float2 m = *reinterpret_cast<const float2*>(means + (b * NL + li) * 2);
        const float2 s = *reinterpret_cast<const float2*>(stds  + (b * NL + li) * 2);
        Entry e;
        e.sd = __floats2half2_rn(s.x, s.y);
        e.mn = __floats2half2_rn(m.x, m.y);
        s_tab[lbl * REP + col] = e;
    }
    __syncthreads();

    const long long v = (long long)blockIdx.x * VPB + (long long)t * VPT;

    const int4 lb = *reinterpret_cast<const int4*>(label + v);

    const float4* np = reinterpret_cast<const float4*>(noise + v * 2);
    const float4 n0 = np[0];
    const float4 n1 = np[1];

    const int col = t & 15;   // fixed conflict-free bank-pair for this lane

    const Entry e0 = s_tab[lb.x * REP + col];
    const Entry e1 = s_tab[lb.y * REP + col];
    const Entry e2 = s_tab[lb.z * REP + col];
    const Entry e3 = s_tab[lb.w * REP + col];

    const float2 s0 = __half22float2(e0.sd), m0 = __half22float2(e0.mn);
    const float2 s1 = __half22float2(e1.sd), m1 = __half22float2(e1.mn);
    const float2 s2 = __half22float2(e2.sd), m2 = __half22float2(e2.mn);
    const float2 s3 = __half22float2(e3.sd), m3 = __half22float2(e3.mn);

    float4 o0, o1;
    o0.x = fmaf(s0.x, n0.x, m0.x);  o0.y = fmaf(s0.y, n0.y, m0.y);
    o0.z = fmaf(s1.x, n0.z, m1.x);  o0.w = fmaf(s1.y, n0.w, m1.y);
    o1.x = fmaf(s2.x, n1.x, m2.x);  o1.y = fmaf(s2.y, n1.y, m2.y);
    o1.z = fmaf(s3.x, n1.z, m3.x);  o1.w = fmaf(s3.y, n1.w, m3.y);

    float4* op = reinterpret_cast<float4*>(out + v * 2);
    op[0] = o0;
    op[1] = o1;
}

extern "C" void kernel_launch(void* const* d_in, const int* in_sizes, int n_in,
                              void* d_out, int out_size)
{
    const int*   label = (const int*)  d_in[0];  // [2,160,160,160,1]
    const float* means = (const float*)d_in[1];  // [2,25,2]
    const float* stds  = (const float*)d_in[2];  // [2,25,2]
    const float* noise = (const float*)d_in[3];  // [2,160,160,160,2]
    float*       out   = (float*)d_out;

    const int blocks = 2 * BLOCKS_PER_BATCH;     // 8000
    gmm_sample_kernel<<<blocks, 256>>>(label, means, stds, noise, out);
}

// round 10
// speedup vs baseline: 1.0483x; 1.0483x over previous
#include <cuda_runtime.h>

// SampleConditionalGMM: out = stds[b, lut[label], c] * noise + means[b, lut[label], c]
// Shapes: label_map [2,160,160,160,1] i32, means/stds [2,25,2] f32,
//         noise/out [2,160,160,160,2] f32.
//
// Gather strategy (R3, measured best): one float4 {std0,std1,mean0,mean1} per
// label VALUE, replicated 8x across float4-columns of the shared crossbar.
// Each thread reads s_tab[lbl*8 + (tid&7)]: every 8-lane phase of the LDS.128
// hits 8 distinct columns -> conflict-free for ANY label mix.
// R9 deltas: pure 32-bit indexing (no 64-bit IMAD chains) + streaming cache
// hints (__ldcs/__stcs) since no array has any reuse.

#define NL 25          // number of generation labels
#define MAXL 48        // max label value + 1
#define REP 8          // replication factor (float4 columns per 128B row)
#define VOX 4096000    // 160*160*160 voxels per batch
#define VPT 4          // voxels per thread
#define VPB 1024       // voxels per block (256 threads * 4)
#define BLOCKS_PER_BATCH (VOX / VPB)   // 4000

__constant__ int c_gen_labels[NL] = {
    0, 2, 3, 4, 5, 7, 8, 10, 11, 12, 13, 14, 15, 16, 17, 18,
    24, 26, 28, 41, 42, 43, 44, 46, 47
};

__global__ __launch_bounds__(256)
void gmm_sample_kernel(const int*   __restrict__ label,
                       const float* __restrict__ means,
                       const float* __restrict__ stds,
                       const float* __restrict__ noise,
                       float*       __restrict__ out)
{
    __shared__ float4 s_tab[MAXL * REP];   // 6144 B

    const int t = threadIdx.x;
    const int b = blockIdx.x / BLOCKS_PER_BATCH;   // batch id, constant per block

    // Fill: 25 labels x 8 replicas = 200 float4, one STS.128 per thread.
    if (t < NL * REP) {
        const int li  = t >> 3;        // compacted label index 0..24
        const int col = t & 7;         // replica column
        const int lbl = c_gen_labels[li];
        const float2 m = *reinterpret_cast<const float2*>(means + (b * NL + li) * 2);
        const float2 s = *reinterpret_cast<const float2*>(stds  + (b * NL + li) * 2);
        s_tab[lbl * REP + col] = make_float4(s.x, s.y, m.x, m.y);
    }
    __syncthreads();

    // All offsets fit in 32 bits: max element index = 2*VOX*2 = 32.8M.
    const int v = blockIdx.x * VPB + t * VPT;

    const int4 lb = __ldcs(reinterpret_cast<const int4*>(label + v));

    const float4* np = reinterpret_cast<const float4*>(noise + v * 2);
    const float4 n0 = __ldcs(np);
    const float4 n1 = __ldcs(np + 1);

    const int col = t & 7;   // fixed conflict-free column for this lane

    const float4 t0 = s_tab[lb.x * REP + col];
    const float4 t1 = s_tab[lb.y * REP + col];
    const float4 t2 = s_tab[lb.z * REP + col];
    const float4 t3 = s_tab[lb.w * REP + col];

    float4 o0, o1;
    o0.x = fmaf(t0.x, n0.x, t0.z);  o0.y = fmaf(t0.y, n0.y, t0.w);
    o0.z = fmaf(t1.x, n0.z, t1.z);  o0.w = fmaf(t1.y, n0.w, t1.w);
    o1.x = fmaf(t2.x, n1.x, t2.z);  o1.y = fmaf(t2.y, n1.y, t2.w);
    o1.z = fmaf(t3.x, n1.z, t3.z);  o1.w = fmaf(t3.y, n1.w, t3.w);

    float4* op = reinterpret_cast<float4*>(out + v * 2);
    __stcs(op,     o0);
    __stcs(op + 1, o1);
}

extern "C" void kernel_launch(void* const* d_in, const int* in_sizes, int n_in,
                              void* d_out, int out_size)
{
    const int*   label = (const int*)  d_in[0];  // [2,160,160,160,1]
    const float* means = (const float*)d_in[1];  // [2,25,2]
    const float* stds  = (const float*)d_in[2];  // [2,25,2]
    const float* noise = (const float*)d_in[3];  // [2,160,160,160,2]
    float*       out   = (float*)d_out;

    const int blocks = 2 * BLOCKS_PER_BATCH;     // 8000
    gmm_sample_kernel<<<blocks, 256>>>(label, means, stds, noise, out);
}